// round 1
// baseline (speedup 1.0000x reference)
#include <cuda_runtime.h>

// LSTM_74122545594502: 3-layer bidirectional LSTM, B=4096 T=256 D=4 H=16.
// Design: 64-thread CTA = 8 batch chains of one direction. Thread t owns gate
// row t (i/f/g/o order) for all 3 layers, weights in registers. Chain pairs
// packed into f32x2 FFMA2. h/x/gates exchanged through shared memory.

namespace {
constexpr int B_ = 4096;
constexpr int T_ = 256;
constexpr int D_ = 4;
constexpr int H_ = 16;
constexpr int NB = 8;                      // chains per CTA
constexpr int GROUPS_PER_DIR = B_ / NB;    // 512
}

typedef unsigned long long ull;

__device__ __forceinline__ ull pack2(float x, float y) {
    ull r;
    asm("mov.b64 %0, {%1, %2};" : "=l"(r) : "f"(x), "f"(y));
    return r;
}
__device__ __forceinline__ void unpack2(ull v, float& x, float& y) {
    asm("mov.b64 {%0, %1}, %2;" : "=f"(x), "=f"(y) : "l"(v));
}
// d = a*b + c on packed f32x2 (Blackwell packed fp32 path, PTX-only)
__device__ __forceinline__ ull ffma2(ull a, ull b, ull c) {
    ull d;
    asm("fma.rn.f32x2 %0, %1, %2, %3;" : "=l"(d) : "l"(a), "l"(b), "l"(c));
    return d;
}

// sigmoid(v) = 1/(1+exp(-v));  tanh(v) = 2*sigmoid(2v)-1.
// exp->inf is safe: 1/(1+inf) = 0 via __fdividef (rcp-based).
__device__ __forceinline__ float fast_act(float v, bool is_tanh) {
    float arg = is_tanh ? (-2.0f * v) : (-v);
    float e = __expf(arg);
    float r = __fdividef(1.0f, 1.0f + e);
    return is_tanh ? (2.0f * r - 1.0f) : r;
}

struct Params {
    const float* y;
    const float* w[24];  // [dir*12 + {Wih1,Whh1,bih1,bhh1, Wih2,...,bhh3}]
};

// final h of layer 3, [dir][batch][H]
__device__ float g_h3[2][B_][H_];

// Compute the 64 gate pre-activations for one layer across NB chains,
// activate, and store to gates row for this thread.
// in_sm: [IN][NB] floats (32B rows, 16B-aligned). h_in: [H][NB].
template <int IN>
__device__ __forceinline__ void gates_stage(
    const float* in_sm, const float* h_in,
    const float* wih, const float* whh, ull bias_pack,
    float* gates_row, bool is_tanh)
{
    ull a0 = bias_pack, a1 = bias_pack, a2 = bias_pack, a3 = bias_pack;
#pragma unroll
    for (int j = 0; j < IN; ++j) {
        ull wp = pack2(wih[j], wih[j]);
        ulonglong2 v01 = *(const ulonglong2*)(in_sm + j * NB);
        ulonglong2 v23 = *(const ulonglong2*)(in_sm + j * NB + 4);
        a0 = ffma2(wp, v01.x, a0);
        a1 = ffma2(wp, v01.y, a1);
        a2 = ffma2(wp, v23.x, a2);
        a3 = ffma2(wp, v23.y, a3);
    }
#pragma unroll
    for (int j = 0; j < H_; ++j) {
        ull wp = pack2(whh[j], whh[j]);
        ulonglong2 v01 = *(const ulonglong2*)(h_in + j * NB);
        ulonglong2 v23 = *(const ulonglong2*)(h_in + j * NB + 4);
        a0 = ffma2(wp, v01.x, a0);
        a1 = ffma2(wp, v01.y, a1);
        a2 = ffma2(wp, v23.x, a2);
        a3 = ffma2(wp, v23.y, a3);
    }
    float g0, g1, g2, g3, g4, g5, g6, g7;
    unpack2(a0, g0, g1);
    unpack2(a1, g2, g3);
    unpack2(a2, g4, g5);
    unpack2(a3, g6, g7);
    float4 r0 = make_float4(fast_act(g0, is_tanh), fast_act(g1, is_tanh),
                            fast_act(g2, is_tanh), fast_act(g3, is_tanh));
    float4 r1 = make_float4(fast_act(g4, is_tanh), fast_act(g5, is_tanh),
                            fast_act(g6, is_tanh), fast_act(g7, is_tanh));
    *(float4*)(gates_row + 0) = r0;
    *(float4*)(gates_row + 4) = r1;
}

__global__ __launch_bounds__(64) void lstm_kernel(Params p) {
    __shared__ float x_sm[2][D_][NB];        // double-buffered inputs
    __shared__ float h_sm[3][H_][NB];        // h state per layer
    __shared__ float gates_sm[64][12];       // 12-float pitch: aligned + low conflict

    const int t   = threadIdx.x;
    const int bid = blockIdx.x;
    const int dir = bid / GROUPS_PER_DIR;
    const int b0  = (bid % GROUPS_PER_DIR) * NB;
    const bool tanh_row = ((t >> 4) == 2);   // rows 32..47 are 'g'

    const float* const* ws = &p.w[dir * 12];

    // Per-thread weights for gate row t, all 3 layers (registers).
    float wih1[D_], whh1[H_], wih2[H_], whh2[H_], wih3[H_], whh3[H_];
#pragma unroll
    for (int j = 0; j < D_; ++j) wih1[j] = ws[0][t * D_ + j];
#pragma unroll
    for (int j = 0; j < H_; ++j) whh1[j] = ws[1][t * H_ + j];
    const float b1 = ws[2][t] + ws[3][t];
#pragma unroll
    for (int j = 0; j < H_; ++j) wih2[j] = ws[4][t * H_ + j];
#pragma unroll
    for (int j = 0; j < H_; ++j) whh2[j] = ws[5][t * H_ + j];
    const float b2 = ws[6][t] + ws[7][t];
#pragma unroll
    for (int j = 0; j < H_; ++j) wih3[j] = ws[8][t * H_ + j];
#pragma unroll
    for (int j = 0; j < H_; ++j) whh3[j] = ws[9][t * H_ + j];
    const float b3 = ws[10][t] + ws[11][t];

    const ull b1p = pack2(b1, b1);
    const ull b2p = pack2(b2, b2);
    const ull b3p = pack2(b3, b3);

    // c-state: threads 0-15 hold layer1 c, 16-31 layer2, 32-47 layer3 (index t&15).
    float cc[NB];
#pragma unroll
    for (int c = 0; c < NB; ++c) cc[c] = 0.0f;

    // zero h state
    for (int i = t; i < 3 * H_ * NB; i += 64) ((float*)h_sm)[i] = 0.0f;

    // stage x for step 0 (threads 32..63: one float each)
    if (t >= 32) {
        int c = (t - 32) >> 2, j = (t - 32) & 3;
        int tt = dir ? (T_ - 1) : 0;
        x_sm[0][j][c] = p.y[((size_t)(b0 + c) * T_ + tt) * D_ + j];
    }
    __syncthreads();

    for (int step = 0; step < T_; ++step) {
        const int buf = step & 1;

        // ---------- layer 1 gates ----------
        gates_stage<D_>(&x_sm[buf][0][0], &h_sm[0][0][0],
                        wih1, whh1, b1p, &gates_sm[t][0], tanh_row);
        __syncthreads();
        if (t < 16) {
            const int l = t;
#pragma unroll
            for (int c = 0; c < NB; ++c) {
                float iv = gates_sm[l][c],      fv = gates_sm[l + 16][c];
                float gv = gates_sm[l + 32][c], ov = gates_sm[l + 48][c];
                float cn = fv * cc[c] + iv * gv;
                cc[c] = cn;
                h_sm[0][l][c] = ov * fast_act(cn, true);
            }
        }
        __syncthreads();

        // ---------- layer 2 gates ----------
        gates_stage<H_>(&h_sm[0][0][0], &h_sm[1][0][0],
                        wih2, whh2, b2p, &gates_sm[t][0], tanh_row);
        __syncthreads();
        if (t >= 16 && t < 32) {
            const int l = t - 16;
#pragma unroll
            for (int c = 0; c < NB; ++c) {
                float iv = gates_sm[l][c],      fv = gates_sm[l + 16][c];
                float gv = gates_sm[l + 32][c], ov = gates_sm[l + 48][c];
                float cn = fv * cc[c] + iv * gv;
                cc[c] = cn;
                h_sm[1][l][c] = ov * fast_act(cn, true);
            }
        }
        __syncthreads();

        // ---------- layer 3 gates (+ prefetch next x) ----------
        gates_stage<H_>(&h_sm[1][0][0], &h_sm[2][0][0],
                        wih3, whh3, b3p, &gates_sm[t][0], tanh_row);
        if (t >= 32 && step + 1 < T_) {
            int c = (t - 32) >> 2, j = (t - 32) & 3;
            int tt = dir ? (T_ - 2 - step) : (step + 1);
            x_sm[buf ^ 1][j][c] = p.y[((size_t)(b0 + c) * T_ + tt) * D_ + j];
        }
        __syncthreads();
        if (t >= 32 && t < 48) {
            const int l = t - 32;
#pragma unroll
            for (int c = 0; c < NB; ++c) {
                float iv = gates_sm[l][c],      fv = gates_sm[l + 16][c];
                float gv = gates_sm[l + 32][c], ov = gates_sm[l + 48][c];
                float cn = fv * cc[c] + iv * gv;
                cc[c] = cn;
                h_sm[2][l][c] = ov * fast_act(cn, true);
            }
        }
        __syncthreads();
    }

    // write final layer-3 h to scratch
    for (int i = t; i < H_ * NB; i += 64) {
        int j = i / NB, c = i % NB;
        g_h3[dir][b0 + c][j] = h_sm[2][j][c];
    }
}

// out[b, k] = b_out[k] + sum_j W_out[k][j]*hf3[b][j] + W_out[k][16+j]*hb3[b][j]
__global__ void proj_kernel(const float* __restrict__ Wo,
                            const float* __restrict__ bo,
                            float* __restrict__ out) {
    int b = blockIdx.x * blockDim.x + threadIdx.x;
    if (b >= B_) return;
    float a0 = bo[0], a1 = bo[1], a2 = bo[2], a3 = bo[3];
#pragma unroll
    for (int j = 0; j < H_; ++j) {
        float hf = g_h3[0][b][j];
        a0 += Wo[0 * 32 + j] * hf;
        a1 += Wo[1 * 32 + j] * hf;
        a2 += Wo[2 * 32 + j] * hf;
        a3 += Wo[3 * 32 + j] * hf;
    }
#pragma unroll
    for (int j = 0; j < H_; ++j) {
        float hb = g_h3[1][b][j];
        a0 += Wo[0 * 32 + 16 + j] * hb;
        a1 += Wo[1 * 32 + 16 + j] * hb;
        a2 += Wo[2 * 32 + 16 + j] * hb;
        a3 += Wo[3 * 32 + 16 + j] * hb;
    }
    ((float4*)out)[b] = make_float4(a0, a1, a2, a3);
}

extern "C" void kernel_launch(void* const* d_in, const int* in_sizes, int n_in,
                              void* d_out, int out_size) {
    (void)in_sizes; (void)n_in; (void)out_size;
    Params p;
    p.y = (const float*)d_in[0];
    for (int i = 0; i < 24; ++i) p.w[i] = (const float*)d_in[1 + i];

    lstm_kernel<<<2 * GROUPS_PER_DIR, 64>>>(p);
    proj_kernel<<<(B_ + 127) / 128, 128>>>((const float*)d_in[25],
                                           (const float*)d_in[26],
                                           (float*)d_out);
}